// round 2
// baseline (speedup 1.0000x reference)
#include <cuda_runtime.h>
#include <cuda_bf16.h>
#include <cstdint>

// ---------------------------------------------------------------------------
// Problem constants (B=1)
// ---------------------------------------------------------------------------
#define N_TOK   768
#define DT      447
#define CS      384
#define CZ      128
#define TFD     831           // DT + CS
#define RELD    139           // 66 + 66 + 1 + 6
#define COUT    640           // 384 (s_init) + 128 (a) + 128 (b)

// d_out layout (flattened tuple, fp32):
//   s_input : [768, 831]            @ 0
//   s_init  : [768, 384]            @ 638208
//   z_init  : [768, 768, 128]       @ 933120
//   rel_feat: [768, 768, 139]       @ 76430592
#define OFF_SINPUT  ((size_t)0)
#define OFF_SINIT   ((size_t)638208)
#define OFF_Z       ((size_t)933120)
#define OFF_REL     ((size_t)76430592)

// Scratch (device globals: allocation-free)
__device__ __align__(16) float g_ab[2 * N_TOK * CZ];     // a then b
__device__ __align__(16) float g_Wt[RELD * CZ];          // W_pos transposed [r][c]

// ---------------------------------------------------------------------------
// Kernel 1: build s_input (concat) + transpose W_pos -> g_Wt
// One block per token row; transpose grid-strided across all threads.
// ---------------------------------------------------------------------------
__global__ __launch_bounds__(256)
void prep_kernel(const float* __restrict__ tf,
                 const float* __restrict__ ta,
                 const float* __restrict__ Wpos,
                 float* __restrict__ out)
{
    const int n   = blockIdx.x;
    const int tid = threadIdx.x;

    // row copy: first DT from tf, next CS from ta
    float* dst = out + OFF_SINPUT + (size_t)n * TFD;
    const float* srcA = tf + (size_t)n * DT;
    const float* srcB = ta + (size_t)n * CS;
    for (int d = tid; d < DT; d += 256) dst[d] = __ldg(srcA + d);
    for (int d = tid; d < CS; d += 256) dst[DT + d] = __ldg(srcB + d);

    // W_pos transpose: Wpos [CZ][RELD] -> g_Wt [RELD][CZ]
    int idx = blockIdx.x * 256 + tid;
    if (idx < RELD * CZ) {
        int r = idx >> 7;
        int c = idx & 127;
        g_Wt[idx] = __ldg(Wpos + c * RELD + r);
    }
}

// ---------------------------------------------------------------------------
// Kernel 2: C[768,640] = s_input[768,831] @ Wcat[640,831]^T
//   Wcat rows: [0,384)=W_single, [384,512)=W_left, [512,640)=W_right
// Tiled 64(n) x 32(c), K-tile 16, 256 threads, 4x2 per thread. 240 blocks.
// ---------------------------------------------------------------------------
__global__ __launch_bounds__(256)
void gemm_kernel(const float* __restrict__ A,      // s_input
                 const float* __restrict__ Wsingle,
                 const float* __restrict__ Wleft,
                 const float* __restrict__ Wright,
                 float* __restrict__ out)
{
    __shared__ float As[16][68];
    __shared__ float Bs[16][36];

    const int n0 = blockIdx.y * 64;
    const int c0 = blockIdx.x * 32;
    const int tid = threadIdx.x;
    const int tx = tid & 15;          // 0..15 -> 2 cols each
    const int ty = tid >> 4;          // 0..15 -> 4 rows each

    float acc[4][2];
#pragma unroll
    for (int r = 0; r < 4; ++r) { acc[r][0] = 0.f; acc[r][1] = 0.f; }

    const int kk = tid & 15;
    const int rl = tid >> 4;

    for (int k0 = 0; k0 < TFD; k0 += 16) {
        const int kg = k0 + kk;
        const bool kok = (kg < TFD);
#pragma unroll
        for (int p = 0; p < 4; ++p) {
            int row = rl + p * 16;
            As[kk][row] = kok ? __ldg(A + (size_t)(n0 + row) * TFD + kg) : 0.f;
        }
#pragma unroll
        for (int p = 0; p < 2; ++p) {
            int col = rl + p * 16;
            float bv = 0.f;
            if (kok) {
                int gc = c0 + col;
                const float* wrow;
                if (gc < 384)      wrow = Wsingle + (size_t)gc * TFD;
                else if (gc < 512) wrow = Wleft   + (size_t)(gc - 384) * TFD;
                else               wrow = Wright  + (size_t)(gc - 512) * TFD;
                bv = __ldg(wrow + kg);
            }
            Bs[kk][col] = bv;
        }
        __syncthreads();

#pragma unroll
        for (int k = 0; k < 16; ++k) {
            float4 av = *(const float4*)&As[k][ty * 4];
            float2 bv = *(const float2*)&Bs[k][tx * 2];
            acc[0][0] += av.x * bv.x; acc[0][1] += av.x * bv.y;
            acc[1][0] += av.y * bv.x; acc[1][1] += av.y * bv.y;
            acc[2][0] += av.z * bv.x; acc[2][1] += av.z * bv.y;
            acc[3][0] += av.w * bv.x; acc[3][1] += av.w * bv.y;
        }
        __syncthreads();
    }

#pragma unroll
    for (int r = 0; r < 4; ++r) {
        int n = n0 + ty * 4 + r;
#pragma unroll
        for (int c = 0; c < 2; ++c) {
            int gc = c0 + tx * 2 + c;
            float v = acc[r][c];
            if (gc < 384) {
                out[OFF_SINIT + (size_t)n * 384 + gc] = v;
            } else if (gc < 512) {
                g_ab[(size_t)n * CZ + (gc - 384)] = v;
            } else {
                g_ab[(size_t)N_TOK * CZ + (size_t)n * CZ + (gc - 512)] = v;
            }
        }
    }
}

// ---------------------------------------------------------------------------
// Kernel 3: fused z_init + rel_feat. One block per i.
//   Phase 0: precompute packed (t1,t2,t4,sent) per j into shared (once).
//   Phase A: zero-fill this i's rel block with float4 streaming stores.
//   Phase B: one warp per j: z row (float4) + scatter <=4 ones into rel row.
// ---------------------------------------------------------------------------
__global__ __launch_bounds__(256)
void fused_z_kernel(const float* __restrict__ contact,
                    const int* __restrict__ ti_g,
                    const int* __restrict__ ri_g,
                    const int* __restrict__ ai_g,
                    const int* __restrict__ ei_g,
                    const int* __restrict__ si_g,
                    const float* __restrict__ Wbond,
                    float* __restrict__ out)
{
    __shared__ int sh_pack[N_TOK];

    const int i    = blockIdx.x;
    const int tid  = threadIdx.x;
    const int lane = tid & 31;
    const int wid  = tid >> 5;

    const int ti = __ldg(ti_g + i), ri = __ldg(ri_g + i), ai = __ldg(ai_g + i);
    const int ei = __ldg(ei_g + i), si = __ldg(si_g + i);

    // Phase 0: per-j packed relative indices
    for (int j = tid; j < N_TOK; j += 256) {
        const int tj = __ldg(ti_g + j), rj = __ldg(ri_g + j), aj = __ldg(ai_g + j);
        const int ej = __ldg(ei_g + j), sj = __ldg(si_g + j);
        const bool sc   = (ai == aj);
        const bool sres = (ri == rj);
        const bool sent = (ei == ej);
        int rd = ri - rj + 32; rd = rd < 0 ? 0 : (rd > 64 ? 64 : rd); if (!sc) rd = 65;
        int td = ti - tj + 32; td = td < 0 ? 0 : (td > 64 ? 64 : td); if (!(sc && sres)) td = 65;
        int cd = si - sj + 2;  cd = cd < 0 ? 0 : (cd > 4  ? 4  : cd); if (!sent) cd = 5;
        sh_pack[j] = rd | ((66 + td) << 8) | ((133 + cd) << 16) | (sent ? (1 << 24) : 0);
    }

    // Phase A: zero-fill rel block (768*139 floats = 26688 float4, 16B aligned)
    float4* relv = (float4*)(out + OFF_REL + (size_t)i * N_TOK * RELD);
    const float4 z4 = make_float4(0.f, 0.f, 0.f, 0.f);
    for (int idx = tid; idx < (N_TOK * RELD) / 4; idx += 256)
        __stcs(relv + idx, z4);

    __syncthreads();

    // Phase B: z rows + scatter ones
    const int lane4 = lane * 4;
    const float4 a4    = *(const float4*)(g_ab + (size_t)i * CZ + lane4);
    const float4 bond4 = *(const float4*)(Wbond + lane4);
    const float4 w132  = *(const float4*)(g_Wt + 132 * CZ + lane4);

    const float* __restrict__ bmat = g_ab + (size_t)N_TOK * CZ;
    float* __restrict__ zout   = out + OFF_Z   + (size_t)i * N_TOK * CZ;
    float* __restrict__ relout = out + OFF_REL + (size_t)i * N_TOK * RELD;
    const float* __restrict__ crow = contact + (size_t)i * N_TOK;

#pragma unroll 2
    for (int j = wid; j < N_TOK; j += 8) {
        const int p  = sh_pack[j];
        const int t1 = p & 0xFF;
        const int t2 = (p >> 8) & 0xFF;
        const int t4 = (p >> 16) & 0xFF;
        const float sef = (p >> 24) ? 1.f : 0.f;

        const float4 w1 = __ldg((const float4*)(g_Wt + (size_t)t1 * CZ + lane4));
        const float4 w2 = __ldg((const float4*)(g_Wt + (size_t)t2 * CZ + lane4));
        const float4 w4 = __ldg((const float4*)(g_Wt + (size_t)t4 * CZ + lane4));
        const float4 b4 = __ldg((const float4*)(bmat + (size_t)j * CZ + lane4));
        const float  cm = __ldg(crow + j);

        float4 z;
        z.x = a4.x + b4.x + w1.x + w2.x + sef * w132.x + w4.x + cm * bond4.x;
        z.y = a4.y + b4.y + w1.y + w2.y + sef * w132.y + w4.y + cm * bond4.y;
        z.z = a4.z + b4.z + w1.z + w2.z + sef * w132.z + w4.z + cm * bond4.z;
        z.w = a4.w + b4.w + w1.w + w2.w + sef * w132.w + w4.w + cm * bond4.w;

        __stcs((float4*)(zout + (size_t)j * CZ + lane4), z);

        // scatter the ones (rel block already zero-filled)
        float* relrow = relout + (size_t)j * RELD;
        if (lane == 0) relrow[t1] = 1.f;
        else if (lane == 1) relrow[t2] = 1.f;
        else if (lane == 2) relrow[t4] = 1.f;
        else if (lane == 3) { if (p >> 24) relrow[132] = 1.f; }
    }
}

// ---------------------------------------------------------------------------
// Launch
// ---------------------------------------------------------------------------
extern "C" void kernel_launch(void* const* d_in, const int* in_sizes, int n_in,
                              void* d_out, int out_size)
{
    const float* tf      = (const float*)d_in[0];   // target_feat
    const float* ta      = (const float*)d_in[1];   // token_act
    const float* contact = (const float*)d_in[2];   // contact_matrix
    const int*   ti      = (const int*)  d_in[3];   // token_index
    const int*   ri      = (const int*)  d_in[4];   // residue_index
    const int*   ai      = (const int*)  d_in[5];   // asym_id
    const int*   ei      = (const int*)  d_in[6];   // entity_id
    const int*   si      = (const int*)  d_in[7];   // sym_id
    const float* Wsingle = (const float*)d_in[8];
    const float* Wleft   = (const float*)d_in[9];
    const float* Wright  = (const float*)d_in[10];
    const float* Wpos    = (const float*)d_in[11];
    const float* Wbond   = (const float*)d_in[12];
    float* out = (float*)d_out;

    prep_kernel<<<N_TOK, 256>>>(tf, ta, Wpos, out);

    dim3 ggrid(COUT / 32, N_TOK / 64);   // 20 x 12 = 240 blocks
    gemm_kernel<<<ggrid, 256>>>(out + OFF_SINPUT, Wsingle, Wleft, Wright, out);

    fused_z_kernel<<<N_TOK, 256>>>(contact, ti, ri, ai, ei, si, Wbond, out);
}

// round 3
// speedup vs baseline: 1.1537x; 1.1537x over previous
#include <cuda_runtime.h>
#include <cuda_bf16.h>
#include <cstdint>

// ---------------------------------------------------------------------------
// Problem constants (B=1)
// ---------------------------------------------------------------------------
#define N_TOK   768
#define DT      447
#define CS      384
#define CZ      128
#define TFD     831           // DT + CS
#define RELD    139           // 66 + 66 + 1 + 6
#define COUT    640           // 384 (s_init) + 128 (a) + 128 (b)

// d_out layout (flattened tuple, fp32):
#define OFF_SINPUT  ((size_t)0)
#define OFF_SINIT   ((size_t)638208)
#define OFF_Z       ((size_t)933120)
#define OFF_REL     ((size_t)76430592)

// Scratch (device globals: allocation-free)
__device__ __align__(16) float g_ab[2 * N_TOK * CZ];     // a then b
__device__ __align__(16) float g_Wt[RELD * CZ];          // W_pos transposed [r][c]

// ---------------------------------------------------------------------------
// relative-feature pack: rd | (66+td)<<8 | (133+cd)<<16 | sent<<24
// ---------------------------------------------------------------------------
__device__ __forceinline__ int make_pack(int ti, int ri, int ai, int ei, int si,
                                         int tj, int rj, int aj, int ej, int sj)
{
    const bool sc   = (ai == aj);
    const bool sres = (ri == rj);
    const bool sent = (ei == ej);
    int rd = ri - rj + 32; rd = rd < 0 ? 0 : (rd > 64 ? 64 : rd); if (!sc) rd = 65;
    int td = ti - tj + 32; td = td < 0 ? 0 : (td > 64 ? 64 : td); if (!(sc && sres)) td = 65;
    int cd = si - sj + 2;  cd = cd < 0 ? 0 : (cd > 4  ? 4  : cd); if (!sent) cd = 5;
    return rd | ((66 + td) << 8) | ((133 + cd) << 16) | (sent ? (1 << 24) : 0);
}

// ---------------------------------------------------------------------------
// Kernel 1: build s_input (concat) + transpose W_pos -> g_Wt
// ---------------------------------------------------------------------------
__global__ __launch_bounds__(256)
void prep_kernel(const float* __restrict__ tf,
                 const float* __restrict__ ta,
                 const float* __restrict__ Wpos,
                 float* __restrict__ out)
{
    const int n   = blockIdx.x;
    const int tid = threadIdx.x;

    float* dst = out + OFF_SINPUT + (size_t)n * TFD;
    const float* srcA = tf + (size_t)n * DT;
    const float* srcB = ta + (size_t)n * CS;
    for (int d = tid; d < DT; d += 256) dst[d] = __ldg(srcA + d);
    for (int d = tid; d < CS; d += 256) dst[DT + d] = __ldg(srcB + d);

    int idx = blockIdx.x * 256 + tid;
    if (idx < RELD * CZ) {
        int r = idx >> 7;
        int c = idx & 127;
        g_Wt[idx] = __ldg(Wpos + c * RELD + r);
    }
}

// ---------------------------------------------------------------------------
// Kernel 2: C[768,640] = s_input @ Wcat^T ; 64x32 tiles, 240 blocks
// ---------------------------------------------------------------------------
__global__ __launch_bounds__(256)
void gemm_kernel(const float* __restrict__ A,
                 const float* __restrict__ Wsingle,
                 const float* __restrict__ Wleft,
                 const float* __restrict__ Wright,
                 float* __restrict__ out)
{
    __shared__ float As[16][68];
    __shared__ float Bs[16][36];

    const int n0 = blockIdx.y * 64;
    const int c0 = blockIdx.x * 32;
    const int tid = threadIdx.x;
    const int tx = tid & 15;
    const int ty = tid >> 4;

    float acc[4][2];
#pragma unroll
    for (int r = 0; r < 4; ++r) { acc[r][0] = 0.f; acc[r][1] = 0.f; }

    const int kk = tid & 15;
    const int rl = tid >> 4;

    for (int k0 = 0; k0 < TFD; k0 += 16) {
        const int kg = k0 + kk;
        const bool kok = (kg < TFD);
#pragma unroll
        for (int p = 0; p < 4; ++p) {
            int row = rl + p * 16;
            As[kk][row] = kok ? __ldg(A + (size_t)(n0 + row) * TFD + kg) : 0.f;
        }
#pragma unroll
        for (int p = 0; p < 2; ++p) {
            int col = rl + p * 16;
            float bv = 0.f;
            if (kok) {
                int gc = c0 + col;
                const float* wrow;
                if (gc < 384)      wrow = Wsingle + (size_t)gc * TFD;
                else if (gc < 512) wrow = Wleft   + (size_t)(gc - 384) * TFD;
                else               wrow = Wright  + (size_t)(gc - 512) * TFD;
                bv = __ldg(wrow + kg);
            }
            Bs[kk][col] = bv;
        }
        __syncthreads();

#pragma unroll
        for (int k = 0; k < 16; ++k) {
            float4 av = *(const float4*)&As[k][ty * 4];
            float2 bv = *(const float2*)&Bs[k][tx * 2];
            acc[0][0] += av.x * bv.x; acc[0][1] += av.x * bv.y;
            acc[1][0] += av.y * bv.x; acc[1][1] += av.y * bv.y;
            acc[2][0] += av.z * bv.x; acc[2][1] += av.z * bv.y;
            acc[3][0] += av.w * bv.x; acc[3][1] += av.w * bv.y;
        }
        __syncthreads();
    }

#pragma unroll
    for (int r = 0; r < 4; ++r) {
        int n = n0 + ty * 4 + r;
#pragma unroll
        for (int c = 0; c < 2; ++c) {
            int gc = c0 + tx * 2 + c;
            float v = acc[r][c];
            if (gc < 384)      out[OFF_SINIT + (size_t)n * 384 + gc] = v;
            else if (gc < 512) g_ab[(size_t)n * CZ + (gc - 384)] = v;
            else               g_ab[(size_t)N_TOK * CZ + (size_t)n * CZ + (gc - 512)] = v;
        }
    }
}

// ---------------------------------------------------------------------------
// Kernel 3: z_init only. One block per i, one warp per j.
// ---------------------------------------------------------------------------
__global__ __launch_bounds__(256)
void z_kernel(const float* __restrict__ contact,
              const int* __restrict__ ti_g,
              const int* __restrict__ ri_g,
              const int* __restrict__ ai_g,
              const int* __restrict__ ei_g,
              const int* __restrict__ si_g,
              const float* __restrict__ Wbond,
              float* __restrict__ out)
{
    __shared__ int sh_pack[N_TOK];

    const int i    = blockIdx.x;
    const int tid  = threadIdx.x;
    const int lane = tid & 31;
    const int wid  = tid >> 5;

    const int ti = __ldg(ti_g + i), ri = __ldg(ri_g + i), ai = __ldg(ai_g + i);
    const int ei = __ldg(ei_g + i), si = __ldg(si_g + i);

    for (int j = tid; j < N_TOK; j += 256) {
        sh_pack[j] = make_pack(ti, ri, ai, ei, si,
                               __ldg(ti_g + j), __ldg(ri_g + j), __ldg(ai_g + j),
                               __ldg(ei_g + j), __ldg(si_g + j));
    }
    __syncthreads();

    const int lane4 = lane * 4;
    const float4 a4    = *(const float4*)(g_ab + (size_t)i * CZ + lane4);
    const float4 bond4 = *(const float4*)(Wbond + lane4);
    const float4 w132  = *(const float4*)(g_Wt + 132 * CZ + lane4);

    const float* __restrict__ bmat = g_ab + (size_t)N_TOK * CZ;
    float* __restrict__ zout = out + OFF_Z + (size_t)i * N_TOK * CZ;
    const float* __restrict__ crow = contact + (size_t)i * N_TOK;

#pragma unroll 2
    for (int j = wid; j < N_TOK; j += 8) {
        const int p  = sh_pack[j];
        const int t1 = p & 0xFF;
        const int t2 = (p >> 8) & 0xFF;
        const int t4 = (p >> 16) & 0xFF;
        const float sef = (p >> 24) ? 1.f : 0.f;

        const float4 w1 = __ldg((const float4*)(g_Wt + (size_t)t1 * CZ + lane4));
        const float4 w2 = __ldg((const float4*)(g_Wt + (size_t)t2 * CZ + lane4));
        const float4 w4 = __ldg((const float4*)(g_Wt + (size_t)t4 * CZ + lane4));
        const float4 b4 = __ldg((const float4*)(bmat + (size_t)j * CZ + lane4));
        const float  cm = __ldg(crow + j);

        float4 z;
        z.x = a4.x + b4.x + w1.x + w2.x + sef * w132.x + w4.x + cm * bond4.x;
        z.y = a4.y + b4.y + w1.y + w2.y + sef * w132.y + w4.y + cm * bond4.y;
        z.z = a4.z + b4.z + w1.z + w2.z + sef * w132.z + w4.z + cm * bond4.z;
        z.w = a4.w + b4.w + w1.w + w2.w + sef * w132.w + w4.w + cm * bond4.w;

        __stcs((float4*)(zout + (size_t)j * CZ + lane4), z);
    }
}

// ---------------------------------------------------------------------------
// Kernel 4: rel_feat, dense float4 streaming writes.
// One block per i. Each float4 element's value recomputed from sh_pack.
// ---------------------------------------------------------------------------
#define REL_V4  ((N_TOK * RELD) / 4)   // 26688 float4 per i

__global__ __launch_bounds__(256)
void rel_kernel(const int* __restrict__ ti_g,
                const int* __restrict__ ri_g,
                const int* __restrict__ ai_g,
                const int* __restrict__ ei_g,
                const int* __restrict__ si_g,
                float* __restrict__ out)
{
    __shared__ int sh_pack[N_TOK];

    const int i   = blockIdx.x;
    const int tid = threadIdx.x;

    const int ti = __ldg(ti_g + i), ri = __ldg(ri_g + i), ai = __ldg(ai_g + i);
    const int ei = __ldg(ei_g + i), si = __ldg(si_g + i);

    for (int j = tid; j < N_TOK; j += 256) {
        sh_pack[j] = make_pack(ti, ri, ai, ei, si,
                               __ldg(ti_g + j), __ldg(ri_g + j), __ldg(ai_g + j),
                               __ldg(ei_g + j), __ldg(si_g + j));
    }
    __syncthreads();

    float4* relv = (float4*)(out + OFF_REL + (size_t)i * N_TOK * RELD);

    for (int idx = tid; idx < REL_V4; idx += 256) {
        const int lin = idx * 4;
        float v[4];
#pragma unroll
        for (int k = 0; k < 4; ++k) {
            const int t_lin = lin + k;
            const int j   = (int)((unsigned)t_lin / 139u);   // magic-mul
            const int t   = t_lin - j * 139;
            const int p   = sh_pack[j];
            const int t1  = p & 0xFF;
            const int t2  = (p >> 8) & 0xFF;
            const int t4  = (p >> 16) & 0xFF;
            float val = 0.f;
            if (t == t1 || t == t2 || t == t4) val = 1.f;
            else if (t == 132 && (p >> 24))    val = 1.f;
            v[k] = val;
        }
        __stcs(relv + idx, make_float4(v[0], v[1], v[2], v[3]));
    }
}

// ---------------------------------------------------------------------------
// Launch
// ---------------------------------------------------------------------------
extern "C" void kernel_launch(void* const* d_in, const int* in_sizes, int n_in,
                              void* d_out, int out_size)
{
    const float* tf      = (const float*)d_in[0];
    const float* ta      = (const float*)d_in[1];
    const float* contact = (const float*)d_in[2];
    const int*   ti      = (const int*)  d_in[3];
    const int*   ri      = (const int*)  d_in[4];
    const int*   ai      = (const int*)  d_in[5];
    const int*   ei      = (const int*)  d_in[6];
    const int*   si      = (const int*)  d_in[7];
    const float* Wsingle = (const float*)d_in[8];
    const float* Wleft   = (const float*)d_in[9];
    const float* Wright  = (const float*)d_in[10];
    const float* Wpos    = (const float*)d_in[11];
    const float* Wbond   = (const float*)d_in[12];
    float* out = (float*)d_out;

    prep_kernel<<<N_TOK, 256>>>(tf, ta, Wpos, out);

    dim3 ggrid(COUT / 32, N_TOK / 64);   // 20 x 12 = 240 blocks
    gemm_kernel<<<ggrid, 256>>>(out + OFF_SINPUT, Wsingle, Wleft, Wright, out);

    z_kernel<<<N_TOK, 256>>>(contact, ti, ri, ai, ei, si, Wbond, out);

    rel_kernel<<<N_TOK, 256>>>(ti, ri, ai, ei, si, out);
}

// round 5
// speedup vs baseline: 1.5947x; 1.3822x over previous
#include <cuda_runtime.h>
#include <cuda_bf16.h>
#include <cstdint>

// ---------------------------------------------------------------------------
// Problem constants (B=1)
// ---------------------------------------------------------------------------
#define N_TOK   768
#define DT      447
#define CS      384
#define CZ      128
#define TFD     831           // DT + CS
#define RELD    139           // 66 + 66 + 1 + 6
#define COUT    640           // 384 (s_init) + 128 (a) + 128 (b)

// d_out layout (flattened tuple, fp32):
#define OFF_SINPUT  ((size_t)0)
#define OFF_SINIT   ((size_t)638208)
#define OFF_Z       ((size_t)933120)
#define OFF_REL     ((size_t)76430592)

#define REL_PER_I    (N_TOK * RELD)       // 106752
#define REL_HALF     (REL_PER_I / 2)      // 53376 elements
#define REL_HALF_V4  (REL_HALF / 4)       // 13344 float4

// Scratch (device globals: allocation-free)
__device__ __align__(16) float g_ab[2 * N_TOK * CZ];   // a then b
__device__ __align__(16) float g_Wt[RELD * CZ];        // W_pos^T [r][c]
__device__ __align__(16) float g_Wc[12 * CZ];          // combo: Wt[133+cd] + sent*Wt[132]

// ---------------------------------------------------------------------------
// relative-feature helpers
// ---------------------------------------------------------------------------
__device__ __forceinline__ void rel_indices(int ti, int ri, int ai, int ei, int si,
                                            int tj, int rj, int aj, int ej, int sj,
                                            int& rd, int& td, int& cd, int& sent)
{
    const bool sc   = (ai == aj);
    const bool sres = (ri == rj);
    sent = (ei == ej) ? 1 : 0;
    rd = ri - rj + 32; rd = rd < 0 ? 0 : (rd > 64 ? 64 : rd); if (!sc) rd = 65;
    td = ti - tj + 32; td = td < 0 ? 0 : (td > 64 ? 64 : td); if (!(sc && sres)) td = 65;
    cd = si - sj + 2;  cd = cd < 0 ? 0 : (cd > 4  ? 4  : cd); if (!sent) cd = 5;
}

// ===========================================================================
// K1: block-type multiplexed kernel.
//   [0, 240)        : GEMM 64x32 tiles (A = concat(tf,ta) on the fly)
//   [240, 1776)     : rel_feat half-blocks via shared bitmask
//   [1776, 1872)    : s_input copy (8 rows / block)
//   [1872, 1942)    : g_Wt transpose
//   [1942, 1948)    : g_Wc combo table
// ===========================================================================
#define K1_GEMM_END  240
#define K1_REL_END   1776
#define K1_SIN_END   1872
#define K1_WT_END    1942
#define K1_GRID      1948

__global__ __launch_bounds__(256)
void k1_kernel(const float* __restrict__ tf,
               const float* __restrict__ ta,
               const int* __restrict__ ti_g,
               const int* __restrict__ ri_g,
               const int* __restrict__ ai_g,
               const int* __restrict__ ei_g,
               const int* __restrict__ si_g,
               const float* __restrict__ Wsingle,
               const float* __restrict__ Wleft,
               const float* __restrict__ Wright,
               const float* __restrict__ Wpos,
               float* __restrict__ out)
{
    __shared__ union {
        struct { float As[16][68]; float Bs[16][36]; } g;
        unsigned int mask[N_TOK * 6];                    // 18432 B
    } sh;

    const int bx  = blockIdx.x;
    const int tid = threadIdx.x;

    if (bx < K1_GEMM_END) {
        // ----------------------------- GEMM ------------------------------
        const int n0 = (bx / 20) * 64;
        const int c0 = (bx % 20) * 32;
        const int tx = tid & 15;
        const int ty = tid >> 4;
        const int kk = tid & 15;
        const int rl = tid >> 4;

        float acc[4][2];
#pragma unroll
        for (int r = 0; r < 4; ++r) { acc[r][0] = 0.f; acc[r][1] = 0.f; }

        for (int k0 = 0; k0 < TFD; k0 += 16) {
            const int kg = k0 + kk;
            const bool kok = (kg < TFD);
#pragma unroll
            for (int p = 0; p < 4; ++p) {
                int row = rl + p * 16;
                float av = 0.f;
                if (kok) {
                    int n = n0 + row;
                    av = (kg < DT) ? __ldg(tf + (size_t)n * DT + kg)
                                   : __ldg(ta + (size_t)n * CS + (kg - DT));
                }
                sh.g.As[kk][row] = av;
            }
#pragma unroll
            for (int p = 0; p < 2; ++p) {
                int col = rl + p * 16;
                float bv = 0.f;
                if (kok) {
                    int gc = c0 + col;
                    const float* wrow;
                    if (gc < 384)      wrow = Wsingle + (size_t)gc * TFD;
                    else if (gc < 512) wrow = Wleft   + (size_t)(gc - 384) * TFD;
                    else               wrow = Wright  + (size_t)(gc - 512) * TFD;
                    bv = __ldg(wrow + kg);
                }
                sh.g.Bs[kk][col] = bv;
            }
            __syncthreads();

#pragma unroll
            for (int k = 0; k < 16; ++k) {
                float4 av = *(const float4*)&sh.g.As[k][ty * 4];
                float2 bv = *(const float2*)&sh.g.Bs[k][tx * 2];
                acc[0][0] += av.x * bv.x; acc[0][1] += av.x * bv.y;
                acc[1][0] += av.y * bv.x; acc[1][1] += av.y * bv.y;
                acc[2][0] += av.z * bv.x; acc[2][1] += av.z * bv.y;
                acc[3][0] += av.w * bv.x; acc[3][1] += av.w * bv.y;
            }
            __syncthreads();
        }

#pragma unroll
        for (int r = 0; r < 4; ++r) {
            int n = n0 + ty * 4 + r;
#pragma unroll
            for (int c = 0; c < 2; ++c) {
                int gc = c0 + tx * 2 + c;
                float v = acc[r][c];
                if (gc < 384)      out[OFF_SINIT + (size_t)n * 384 + gc] = v;
                else if (gc < 512) g_ab[(size_t)n * CZ + (gc - 384)] = v;
                else               g_ab[(size_t)N_TOK * CZ + (size_t)n * CZ + (gc - 512)] = v;
            }
        }
    } else if (bx < K1_REL_END) {
        // --------------------------- rel_feat ----------------------------
        const int r  = bx - K1_GEMM_END;
        const int i  = r >> 1;
        const int h  = r & 1;

        const int ti = __ldg(ti_g + i), ri = __ldg(ri_g + i), ai = __ldg(ai_g + i);
        const int ei = __ldg(ei_g + i), si = __ldg(si_g + i);

        // Phase 0: per-row 139-bit masks (generic bit-set; rd can hit word2!)
        for (int j = tid; j < N_TOK; j += 256) {
            int rd, td, cd, sent;
            rel_indices(ti, ri, ai, ei, si,
                        __ldg(ti_g + j), __ldg(ri_g + j), __ldg(ai_g + j),
                        __ldg(ei_g + j), __ldg(si_g + j),
                        rd, td, cd, sent);
            unsigned int m[5] = {0u, 0u, 0u, 0u, 0u};
            m[rd >> 5] |= 1u << (rd & 31);                 // bits 0..65
            const int t2 = 66 + td;                        // bits 66..131
            m[t2 >> 5] |= 1u << (t2 & 31);
            m[4] |= ((unsigned)sent) << 4;                 // bit 132
            m[4] |= 1u << (5 + cd);                        // bits 133..138
            unsigned int* mw = sh.mask + j * 6;
            mw[0] = m[0]; mw[1] = m[1]; mw[2] = m[2];
            mw[3] = m[3]; mw[4] = m[4]; mw[5] = 0u;
        }
        __syncthreads();

        // Phase B: dense float4 streaming stores, incremental (j, t)
        float4* dst = (float4*)(out + OFF_REL + (size_t)i * REL_PER_I) +
                      h * REL_HALF_V4 + tid;
        int lin = h * REL_HALF + tid * 4;
        int j = (int)((unsigned)lin / 139u);     // one division total
        int t = lin - j * 139;

        for (int idx = tid; idx < REL_HALF_V4; idx += 256) {
            unsigned int bits;
            if (t <= 135) {
                const int base = j * 6 + (t >> 5);
                unsigned long long W = (unsigned long long)sh.mask[base] |
                                       ((unsigned long long)sh.mask[base + 1] << 32);
                bits = (unsigned int)(W >> (t & 31)) & 0xFu;
            } else {
                unsigned int a = sh.mask[j * 6 + 4] >> (t - 128);
                unsigned int b = sh.mask[(j + 1) * 6] << (139 - t);
                bits = (a | b) & 0xFu;
            }
            float4 v;
            v.x = (bits & 1u) ? 1.f : 0.f;
            v.y = (bits & 2u) ? 1.f : 0.f;
            v.z = (bits & 4u) ? 1.f : 0.f;
            v.w = (bits & 8u) ? 1.f : 0.f;
            __stcs(dst, v);
            dst += 256;
            j += 7; t += 51;
            if (t >= 139) { t -= 139; ++j; }
        }
    } else if (bx < K1_SIN_END) {
        // --------------------------- s_input -----------------------------
        const int n0 = (bx - K1_REL_END) * 8;
        for (int r = 0; r < 8; ++r) {
            const int n = n0 + r;
            float* dst = out + OFF_SINPUT + (size_t)n * TFD;
            const float* srcA = tf + (size_t)n * DT;
            const float* srcB = ta + (size_t)n * CS;
            for (int d = tid; d < DT; d += 256) dst[d] = __ldg(srcA + d);
            for (int d = tid; d < CS; d += 256) dst[DT + d] = __ldg(srcB + d);
        }
    } else if (bx < K1_WT_END) {
        // ------------------------ g_Wt transpose -------------------------
        int idx = (bx - K1_SIN_END) * 256 + tid;
        if (idx < RELD * CZ) {
            int rr = idx >> 7;
            int c  = idx & 127;
            g_Wt[idx] = __ldg(Wpos + c * RELD + rr);
        }
    } else {
        // ------------------------- combo table ---------------------------
        int idx = (bx - K1_WT_END) * 256 + tid;
        if (idx < 12 * CZ) {
            int combo = idx >> 7;       // sent*6 + cd
            int c     = idx & 127;
            int sent  = combo / 6;
            int cd    = combo - sent * 6;
            float v = __ldg(Wpos + c * RELD + 133 + cd);
            if (sent) v += __ldg(Wpos + c * RELD + 132);
            g_Wc[idx] = v;
        }
    }
}

// ===========================================================================
// K2: z_init. 1536 blocks: i = bx>>1, half h = bx&1 (384 j's each).
// ===========================================================================
__global__ __launch_bounds__(256)
void z_kernel(const float* __restrict__ contact,
              const int* __restrict__ ti_g,
              const int* __restrict__ ri_g,
              const int* __restrict__ ai_g,
              const int* __restrict__ ei_g,
              const int* __restrict__ si_g,
              const float* __restrict__ Wbond,
              float* __restrict__ out)
{
    __shared__ int sh_pack[N_TOK / 2];

    const int bx   = blockIdx.x;
    const int i    = bx >> 1;
    const int h    = bx & 1;
    const int j0   = h * (N_TOK / 2);
    const int tid  = threadIdx.x;
    const int lane = tid & 31;
    const int wid  = tid >> 5;

    const int ti = __ldg(ti_g + i), ri = __ldg(ri_g + i), ai = __ldg(ai_g + i);
    const int ei = __ldg(ei_g + i), si = __ldg(si_g + i);

    for (int jl = tid; jl < N_TOK / 2; jl += 256) {
        const int j = j0 + jl;
        int rd, td, cd, sent;
        rel_indices(ti, ri, ai, ei, si,
                    __ldg(ti_g + j), __ldg(ri_g + j), __ldg(ai_g + j),
                    __ldg(ei_g + j), __ldg(si_g + j),
                    rd, td, cd, sent);
        sh_pack[jl] = rd | ((66 + td) << 8) | ((sent * 6 + cd) << 16);
    }
    __syncthreads();

    const int lane4 = lane * 4;
    const float4 a4    = *(const float4*)(g_ab + (size_t)i * CZ + lane4);
    const float4 bond4 = *(const float4*)(Wbond + lane4);

    const float* __restrict__ bmat = g_ab + (size_t)N_TOK * CZ;
    float* __restrict__ zout = out + OFF_Z + (size_t)i * N_TOK * CZ;
    const float* __restrict__ crow = contact + (size_t)i * N_TOK;

#pragma unroll 2
    for (int jl = wid; jl < N_TOK / 2; jl += 8) {
        const int j  = j0 + jl;
        const int p  = sh_pack[jl];
        const int t1 = p & 0xFF;
        const int t2 = (p >> 8) & 0xFF;
        const int tc = (p >> 16) & 0xFF;

        const float4 w1 = __ldg((const float4*)(g_Wt + (size_t)t1 * CZ + lane4));
        const float4 w2 = __ldg((const float4*)(g_Wt + (size_t)t2 * CZ + lane4));
        const float4 wc = __ldg((const float4*)(g_Wc + (size_t)tc * CZ + lane4));
        const float4 b4 = __ldg((const float4*)(bmat + (size_t)j * CZ + lane4));
        const float  cm = __ldg(crow + j);

        float4 z;
        z.x = a4.x + b4.x + w1.x + w2.x + wc.x + cm * bond4.x;
        z.y = a4.y + b4.y + w1.y + w2.y + wc.y + cm * bond4.y;
        z.z = a4.z + b4.z + w1.z + w2.z + wc.z + cm * bond4.z;
        z.w = a4.w + b4.w + w1.w + w2.w + wc.w + cm * bond4.w;

        __stcs((float4*)(zout + (size_t)j * CZ + lane4), z);
    }
}

// ---------------------------------------------------------------------------
// Launch
// ---------------------------------------------------------------------------
extern "C" void kernel_launch(void* const* d_in, const int* in_sizes, int n_in,
                              void* d_out, int out_size)
{
    const float* tf      = (const float*)d_in[0];
    const float* ta      = (const float*)d_in[1];
    const float* contact = (const float*)d_in[2];
    const int*   ti      = (const int*)  d_in[3];
    const int*   ri      = (const int*)  d_in[4];
    const int*   ai      = (const int*)  d_in[5];
    const int*   ei      = (const int*)  d_in[6];
    const int*   si      = (const int*)  d_in[7];
    const float* Wsingle = (const float*)d_in[8];
    const float* Wleft   = (const float*)d_in[9];
    const float* Wright  = (const float*)d_in[10];
    const float* Wpos    = (const float*)d_in[11];
    const float* Wbond   = (const float*)d_in[12];
    float* out = (float*)d_out;

    k1_kernel<<<K1_GRID, 256>>>(tf, ta, ti, ri, ai, ei, si,
                                Wsingle, Wleft, Wright, Wpos, out);

    z_kernel<<<2 * N_TOK, 256>>>(contact, ti, ri, ai, ei, si, Wbond, out);
}